// round 1
// baseline (speedup 1.0000x reference)
#include <cuda_runtime.h>
#include <cuda_bf16.h>
#include <math.h>

#define MTOT 8192      // B*T
#define CDIM 2048      // H*D
#define T_LEN 4096
#define B_N 2
#define H_N 16
#define D_N 128

// ---------------- scratch buffers (static device memory; no allocation) ----
__device__ float g_bufq[MTOT * CDIM];
__device__ float g_bufk[MTOT * CDIM];
__device__ float g_bufv[MTOT * CDIM];
__device__ float g_cq[MTOT * CDIM];
__device__ float g_ck[MTOT * CDIM];
__device__ float g_cv[MTOT * CDIM];
__device__ float g_gate[MTOT * CDIM];
__device__ float g_gog[MTOT * CDIM];
__device__ float g_fa[MTOT * D_N];
__device__ float g_ga[MTOT * D_N];
__device__ float g_beta[MTOT * H_N];
__device__ float g_oscan[MTOT * CDIM];
__device__ float g_ogated[MTOT * CDIM];

// ---------------- generic fp32 SGEMM: C[M,N] = A[M,K] * B[K,N] --------------
// 128x128 tile, BK=8, 256 threads, 8x8 microtile
__global__ __launch_bounds__(256) void sgemm128(
    const float* __restrict__ A, const float* __restrict__ B,
    float* __restrict__ C, int M, int N, int K) {
  __shared__ float As[8][128];
  __shared__ float Bs[8][128];
  int tid = threadIdx.x;
  int bm = blockIdx.y * 128;
  int bn = blockIdx.x * 128;

  int arow = tid >> 1;            // 0..127
  int acol = (tid & 1) * 4;       // 0 or 4
  int brow = tid >> 5;            // 0..7
  int bcol = (tid & 31) * 4;      // 0..124
  int ty = tid >> 4, tx = tid & 15;

  float acc[8][8];
#pragma unroll
  for (int i = 0; i < 8; i++)
#pragma unroll
    for (int j = 0; j < 8; j++) acc[i][j] = 0.f;

  for (int k0 = 0; k0 < K; k0 += 8) {
    float4 av = make_float4(0.f, 0.f, 0.f, 0.f);
    if (bm + arow < M)
      av = *(const float4*)&A[(size_t)(bm + arow) * K + k0 + acol];
    As[acol + 0][arow] = av.x;
    As[acol + 1][arow] = av.y;
    As[acol + 2][arow] = av.z;
    As[acol + 3][arow] = av.w;

    float4 bv = make_float4(0.f, 0.f, 0.f, 0.f);
    if (bn + bcol < N)
      bv = *(const float4*)&B[(size_t)(k0 + brow) * N + bn + bcol];
    *(float4*)&Bs[brow][bcol] = bv;
    __syncthreads();

#pragma unroll
    for (int kk = 0; kk < 8; kk++) {
      float a[8], b[8];
#pragma unroll
      for (int i = 0; i < 8; i++) a[i] = As[kk][ty * 8 + i];
#pragma unroll
      for (int j = 0; j < 8; j++) b[j] = Bs[kk][tx * 8 + j];
#pragma unroll
      for (int i = 0; i < 8; i++)
#pragma unroll
        for (int j = 0; j < 8; j++) acc[i][j] = fmaf(a[i], b[j], acc[i][j]);
    }
    __syncthreads();
  }

#pragma unroll
  for (int i = 0; i < 8; i++) {
    int r = bm + ty * 8 + i;
    if (r >= M) continue;
#pragma unroll
    for (int j = 0; j < 8; j++) {
      int c = bn + tx * 8 + j;
      if (c < N) C[(size_t)r * N + c] = acc[i][j];
    }
  }
}

// ---------------- depthwise causal conv (K=4) + SiLU -----------------------
__global__ void conv_silu_kernel(const float* __restrict__ x,
                                 const float* __restrict__ w,
                                 float* __restrict__ y) {
  int i = blockIdx.x * blockDim.x + threadIdx.x;
  if (i >= MTOT * CDIM) return;
  int c = i & (CDIM - 1);
  int bt = i >> 11;
  int t = bt & (T_LEN - 1);
  float acc = 0.f;
#pragma unroll
  for (int j = 0; j < 4; j++) {
    int ts = t + j - 3;
    float xv = (ts >= 0) ? x[i + (j - 3) * CDIM] : 0.f;
    acc = fmaf(xv, w[c * 4 + j], acc);
  }
  y[i] = acc / (1.f + expf(-acc));  // silu
}

// ---------------- prep: l2norm(q)*D^-0.5, l2norm(k), gate g, beta ----------
__global__ void prep_kernel(float* __restrict__ q, float* __restrict__ k,
                            float* __restrict__ g, float* __restrict__ beta,
                            const float* __restrict__ A_log,
                            const float* __restrict__ dt_bias) {
  int blk = blockIdx.x;  // bt*16 + h
  int h = blk & 15;
  int bt = blk >> 4;
  int d = threadIdx.x;   // 0..127
  int idx = bt * CDIM + h * D_N + d;

  float qv = q[idx], kv = k[idx];
  float sq = qv * qv, sk = kv * kv;
#pragma unroll
  for (int o = 16; o > 0; o >>= 1) {
    sq += __shfl_xor_sync(0xffffffffu, sq, o);
    sk += __shfl_xor_sync(0xffffffffu, sk, o);
  }
  __shared__ float rq_[4], rk_[4];
  int wid = d >> 5, lane = d & 31;
  if (lane == 0) { rq_[wid] = sq; rk_[wid] = sk; }
  __syncthreads();
  float tq = rq_[0] + rq_[1] + rq_[2] + rq_[3];
  float tk = rk_[0] + rk_[1] + rk_[2] + rk_[3];

  q[idx] = qv * rsqrtf(tq + 1e-6f) * 0.08838834764831845f;  // D^-0.5
  k[idx] = kv * rsqrtf(tk + 1e-6f);

  float gp = g[idx] + dt_bias[h * D_N + d];
  float sp = (gp > 0.f) ? gp + log1pf(expf(-gp)) : log1pf(expf(gp));
  g[idx] = -expf(A_log[h]) * sp;

  if (d == 0) {
    float bp = beta[bt * H_N + h];
    beta[bt * H_N + h] = 1.f / (1.f + expf(-bp));
  }
}

// ---------------- sequential gated delta-rule scan --------------------------
// grid: 32 (b,h) * 4 column groups = 128 blocks; 128 threads each.
// thread t: column cl = t&31 (global j = cg*32+cl), row quarter rq = t>>5
// Keeps S[rows rq*32..rq*32+31][col j] in 32 registers.
__global__ __launch_bounds__(128) void kda_scan_kernel(
    const float* __restrict__ q, const float* __restrict__ k,
    const float* __restrict__ v, const float* __restrict__ g,
    const float* __restrict__ beta, float* __restrict__ o) {
  int bh = blockIdx.x >> 2;
  int cg = blockIdx.x & 3;
  int b = bh >> 4, h = bh & 15;
  int tid = threadIdx.x;
  int cl = tid & 31;
  int rq = tid >> 5;
  int j = cg * 32 + cl;
  int rbase = rq * 32;

  __shared__ float ks[128], qs[128], es[128];
  __shared__ float vs[32], us[32];
  __shared__ float kp[4][32], op[4][32];
  __shared__ float beta_sh;

  float S[32];
#pragma unroll
  for (int i = 0; i < 32; i++) S[i] = 0.f;

  const size_t base = ((size_t)b * T_LEN) * CDIM + h * D_N;
  const size_t baseB = (size_t)b * T_LEN * H_N + h;

  // prefetch t = 0
  float kr = k[base + tid];
  float qr = q[base + tid];
  float gr = g[base + tid];
  float vr = (tid < 32) ? v[base + j] : 0.f;
  float br = (tid == 0) ? beta[baseB] : 0.f;

  for (int t = 0; t < T_LEN; t++) {
    // publish current step to shared
    ks[tid] = kr;
    qs[tid] = qr;
    es[tid] = expf(gr);
    if (tid < 32) vs[cl] = vr;
    if (tid == 0) beta_sh = br;
    __syncthreads();

    // prefetch next step (latency overlapped with compute below)
    if (t + 1 < T_LEN) {
      size_t off2 = base + (size_t)(t + 1) * CDIM;
      kr = k[off2 + tid];
      qr = q[off2 + tid];
      gr = g[off2 + tid];
      if (tid < 32) vr = v[off2 + j];
      if (tid == 0) br = beta[baseB + (size_t)(t + 1) * H_N];
    }

    // pass 1: decay + k.S
    float kd = 0.f;
#pragma unroll
    for (int i = 0; i < 32; i += 4) {
      float4 e4 = *(const float4*)&es[rbase + i];
      float4 k4 = *(const float4*)&ks[rbase + i];
      S[i + 0] *= e4.x; kd = fmaf(k4.x, S[i + 0], kd);
      S[i + 1] *= e4.y; kd = fmaf(k4.y, S[i + 1], kd);
      S[i + 2] *= e4.z; kd = fmaf(k4.z, S[i + 2], kd);
      S[i + 3] *= e4.w; kd = fmaf(k4.w, S[i + 3], kd);
    }
    kp[rq][cl] = kd;
    __syncthreads();

    if (tid < 32) {
      float u = (vs[tid] - (kp[0][tid] + kp[1][tid] + kp[2][tid] + kp[3][tid])) * beta_sh;
      us[tid] = u;
    }
    __syncthreads();

    // pass 2: rank-1 update + q.S
    float u = us[cl];
    float od = 0.f;
#pragma unroll
    for (int i = 0; i < 32; i += 4) {
      float4 k4 = *(const float4*)&ks[rbase + i];
      float4 q4 = *(const float4*)&qs[rbase + i];
      S[i + 0] = fmaf(k4.x, u, S[i + 0]); od = fmaf(q4.x, S[i + 0], od);
      S[i + 1] = fmaf(k4.y, u, S[i + 1]); od = fmaf(q4.y, S[i + 1], od);
      S[i + 2] = fmaf(k4.z, u, S[i + 2]); od = fmaf(q4.z, S[i + 2], od);
      S[i + 3] = fmaf(k4.w, u, S[i + 3]); od = fmaf(q4.w, S[i + 3], od);
    }
    op[rq][cl] = od;
    __syncthreads();

    if (tid < 32)
      o[base + (size_t)t * CDIM + j] =
          op[0][tid] + op[1][tid] + op[2][tid] + op[3][tid];
    // no extra sync needed: next-iter shared writes don't collide with the
    // op[] reads above (disjoint arrays / same-thread ordering).
  }
}

// ---------------- gated RMSNorm: rmsnorm(o)*w*sigmoid(go) -------------------
__global__ void gatenorm_kernel(const float* __restrict__ o,
                                const float* __restrict__ go,
                                const float* __restrict__ w,
                                float* __restrict__ out) {
  int blk = blockIdx.x;   // bt*16 + h
  int d = threadIdx.x;
  int idx = blk * D_N + d;
  float ov = o[idx];
  float s = ov * ov;
#pragma unroll
  for (int off = 16; off > 0; off >>= 1) s += __shfl_xor_sync(0xffffffffu, s, off);
  __shared__ float r_[4];
  int wid = d >> 5, lane = d & 31;
  if (lane == 0) r_[wid] = s;
  __syncthreads();
  float tot = r_[0] + r_[1] + r_[2] + r_[3];
  float rms = rsqrtf(tot * (1.f / 128.f) + 1e-6f);
  float gov = go[idx];
  out[idx] = ov * rms * w[d] * (1.f / (1.f + expf(-gov)));
}

// ---------------- launch ----------------------------------------------------
extern "C" void kernel_launch(void* const* d_in, const int* in_sizes, int n_in,
                              void* d_out, int out_size) {
  const float* x        = (const float*)d_in[0];
  const float* Wq       = (const float*)d_in[1];
  const float* Wk       = (const float*)d_in[2];
  const float* Wv       = (const float*)d_in[3];
  const float* conv_q_w = (const float*)d_in[4];
  const float* conv_k_w = (const float*)d_in[5];
  const float* conv_v_w = (const float*)d_in[6];
  const float* A_log    = (const float*)d_in[7];
  const float* Wfa      = (const float*)d_in[8];
  const float* Wfb      = (const float*)d_in[9];
  const float* dt_bias  = (const float*)d_in[10];
  const float* Wb       = (const float*)d_in[11];
  const float* Wga      = (const float*)d_in[12];
  const float* Wgb      = (const float*)d_in[13];
  const float* o_norm_w = (const float*)d_in[14];
  const float* Wo       = (const float*)d_in[15];
  float* out = (float*)d_out;

  float *bq, *bk, *bv, *cq, *ck, *cv, *gate, *gog, *fa, *ga, *beta, *oscan, *ogated;
  cudaGetSymbolAddress((void**)&bq, g_bufq);
  cudaGetSymbolAddress((void**)&bk, g_bufk);
  cudaGetSymbolAddress((void**)&bv, g_bufv);
  cudaGetSymbolAddress((void**)&cq, g_cq);
  cudaGetSymbolAddress((void**)&ck, g_ck);
  cudaGetSymbolAddress((void**)&cv, g_cv);
  cudaGetSymbolAddress((void**)&gate, g_gate);
  cudaGetSymbolAddress((void**)&gog, g_gog);
  cudaGetSymbolAddress((void**)&fa, g_fa);
  cudaGetSymbolAddress((void**)&ga, g_ga);
  cudaGetSymbolAddress((void**)&beta, g_beta);
  cudaGetSymbolAddress((void**)&oscan, g_oscan);
  cudaGetSymbolAddress((void**)&ogated, g_ogated);

  dim3 gBig(CDIM / 128, MTOT / 128);   // N=2048
  dim3 gN1(1, MTOT / 128);             // N<=128

  // projections
  sgemm128<<<gBig, 256>>>(x, Wq, bq, MTOT, CDIM, CDIM);
  sgemm128<<<gBig, 256>>>(x, Wk, bk, MTOT, CDIM, CDIM);
  sgemm128<<<gBig, 256>>>(x, Wv, bv, MTOT, CDIM, CDIM);
  // low-rank gate paths
  sgemm128<<<gN1, 256>>>(x, Wfa, fa, MTOT, D_N, CDIM);
  sgemm128<<<gBig, 256>>>(fa, Wfb, gate, MTOT, CDIM, D_N);
  sgemm128<<<gN1, 256>>>(x, Wga, ga, MTOT, D_N, CDIM);
  sgemm128<<<gBig, 256>>>(ga, Wgb, gog, MTOT, CDIM, D_N);
  // beta pre-activation
  sgemm128<<<gN1, 256>>>(x, Wb, beta, MTOT, H_N, CDIM);

  // conv + silu
  int nEl = MTOT * CDIM;
  conv_silu_kernel<<<(nEl + 255) / 256, 256>>>(bq, conv_q_w, cq);
  conv_silu_kernel<<<(nEl + 255) / 256, 256>>>(bk, conv_k_w, ck);
  conv_silu_kernel<<<(nEl + 255) / 256, 256>>>(bv, conv_v_w, cv);

  // normalize q/k, finalize gate + beta
  prep_kernel<<<MTOT * H_N, 128>>>(cq, ck, gate, beta, A_log, dt_bias);

  // sequential scan
  kda_scan_kernel<<<128, 128>>>(cq, ck, cv, gate, beta, oscan);

  // gated rmsnorm
  gatenorm_kernel<<<MTOT * H_N, 128>>>(oscan, gog, o_norm_w, ogated);

  // output projection
  sgemm128<<<gBig, 256>>>(ogated, Wo, out, MTOT, CDIM, CDIM);
}

// round 4
// speedup vs baseline: 1.5648x; 1.5648x over previous
#include <cuda_runtime.h>
#include <cuda_bf16.h>
#include <math.h>
#include <cstdint>

#define MTOT 8192      // B*T
#define CDIM 2048      // H*D
#define T_LEN 4096
#define H_N 16
#define D_N 128

typedef __nv_bfloat16 bf16;

// ====================== scratch (static device memory) ======================
__device__ float g_bufq[MTOT * CDIM];
__device__ float g_bufk[MTOT * CDIM];
__device__ float g_bufv[MTOT * CDIM];
__device__ float g_cq[MTOT * CDIM];
__device__ float g_ck[MTOT * CDIM];
__device__ float g_cv[MTOT * CDIM];
__device__ float g_gate[MTOT * CDIM];
__device__ float g_gog[MTOT * CDIM];
__device__ float g_fa[MTOT * D_N];
__device__ float g_ga[MTOT * D_N];
__device__ float g_beta[MTOT * H_N];
__device__ float g_oscan[MTOT * CDIM];
__device__ float g_ogated[MTOT * CDIM];
// bf16 hi/lo split operands
__device__ bf16 g_xh[MTOT * CDIM];
__device__ bf16 g_xl[MTOT * CDIM];
__device__ bf16 g_oh[MTOT * CDIM];
__device__ bf16 g_ol[MTOT * CDIM];
__device__ bf16 g_fah[MTOT * D_N];
__device__ bf16 g_fal[MTOT * D_N];
__device__ bf16 g_gah[MTOT * D_N];
__device__ bf16 g_gal[MTOT * D_N];
// transposed + split weights (row n = W[:,n], K contiguous)
__device__ bf16 g_WqTh[CDIM * CDIM];
__device__ bf16 g_WqTl[CDIM * CDIM];
__device__ bf16 g_WkTh[CDIM * CDIM];
__device__ bf16 g_WkTl[CDIM * CDIM];
__device__ bf16 g_WvTh[CDIM * CDIM];
__device__ bf16 g_WvTl[CDIM * CDIM];
__device__ bf16 g_WoTh[CDIM * CDIM];
__device__ bf16 g_WoTl[CDIM * CDIM];
__device__ bf16 g_WfaTh[D_N * CDIM];
__device__ bf16 g_WfaTl[D_N * CDIM];
__device__ bf16 g_WgaTh[D_N * CDIM];
__device__ bf16 g_WgaTl[D_N * CDIM];
__device__ bf16 g_WfbTh[CDIM * D_N];
__device__ bf16 g_WfbTl[CDIM * D_N];
__device__ bf16 g_WgbTh[CDIM * D_N];
__device__ bf16 g_WgbTl[CDIM * D_N];
__device__ bf16 g_WbTh[H_N * CDIM];
__device__ bf16 g_WbTl[H_N * CDIM];

// ====================== helpers ============================================
__device__ __forceinline__ uint32_t smem_u32(const void* p) {
  uint32_t a;
  asm("{ .reg .u64 t; cvta.to.shared.u64 t, %1; cvt.u32.u64 %0, t; }"
      : "=r"(a) : "l"(p));
  return a;
}
__device__ __forceinline__ void cp16(uint32_t dst, const void* src, bool valid) {
  int sz = valid ? 16 : 0;
  asm volatile("cp.async.cg.shared.global [%0], [%1], 16, %2;"
               :: "r"(dst), "l"(src), "r"(sz) : "memory");
}
__device__ __forceinline__ void ldsm4(uint32_t* r, uint32_t addr) {
  asm volatile("ldmatrix.sync.aligned.m8n8.x4.shared.b16 {%0,%1,%2,%3}, [%4];"
               : "=r"(r[0]), "=r"(r[1]), "=r"(r[2]), "=r"(r[3]) : "r"(addr));
}
__device__ __forceinline__ void mma16816(float* c, const uint32_t* a,
                                         const uint32_t* b) {
  asm volatile(
      "mma.sync.aligned.m16n8k16.row.col.f32.bf16.bf16.f32 "
      "{%0,%1,%2,%3},{%4,%5,%6,%7},{%8,%9},{%0,%1,%2,%3};"
      : "+f"(c[0]), "+f"(c[1]), "+f"(c[2]), "+f"(c[3])
      : "r"(a[0]), "r"(a[1]), "r"(a[2]), "r"(a[3]), "r"(b[0]), "r"(b[1]));
}

// ====================== bf16 hi/lo split (contiguous) =======================
__global__ void split_kernel(const float* __restrict__ src,
                             bf16* __restrict__ h, bf16* __restrict__ l, int n) {
  int i = (blockIdx.x * blockDim.x + threadIdx.x) * 4;
  if (i >= n) return;
  float4 f = *(const float4*)&src[i];
  bf16 h0 = __float2bfloat16(f.x), h1 = __float2bfloat16(f.y);
  bf16 h2 = __float2bfloat16(f.z), h3 = __float2bfloat16(f.w);
  __nv_bfloat162 hh0 = {h0, h1}, hh1 = {h2, h3};
  __nv_bfloat162 ll0 = {__float2bfloat16(f.x - __bfloat162float(h0)),
                        __float2bfloat16(f.y - __bfloat162float(h1))};
  __nv_bfloat162 ll1 = {__float2bfloat16(f.z - __bfloat162float(h2)),
                        __float2bfloat16(f.w - __bfloat162float(h3))};
  *(__nv_bfloat162*)&h[i] = hh0; *(__nv_bfloat162*)&h[i + 2] = hh1;
  *(__nv_bfloat162*)&l[i] = ll0; *(__nv_bfloat162*)&l[i + 2] = ll1;
}

// ============== transpose + split: dst[c][r] = split(src[r][c]) =============
__global__ void transpose_split(const float* __restrict__ src,
                                bf16* __restrict__ dh, bf16* __restrict__ dl,
                                int rows, int cols) {
  __shared__ float t[32][33];
  int bx = blockIdx.x * 32, by = blockIdx.y * 32;
  int tx = threadIdx.x;
  for (int j = threadIdx.y; j < 32; j += 8) {
    int r = by + j, c = bx + tx;
    if (r < rows && c < cols) t[j][tx] = src[(size_t)r * cols + c];
  }
  __syncthreads();
  int ro = by + tx;
  for (int j = threadIdx.y; j < 32; j += 8) {
    int c = bx + j;
    if (c < cols && ro < rows) {
      float v = t[tx][j];
      bf16 h = __float2bfloat16(v);
      dh[(size_t)c * rows + ro] = h;
      dl[(size_t)c * rows + ro] = __float2bfloat16(v - __bfloat162float(h));
    }
  }
}

// ====================== bf16 mma.sync GEMM (3-term split) ===================
// C[M,N] = A[M,K]*Bt[N,K]^T using (AhBh + AhBl + AlBh).
// Tile 128x128, BK=32, 8 warps (2x4), warp tile 64x32. Double-buffered smem.
// smem tile row padded to 80B -> conflict-free ldmatrix.
#define TILE_B 10240          // one 128x32 bf16 tile (80B rows)
#define BUF_B  (4 * TILE_B)   // Ah, Al, Bh, Bl
__global__ __launch_bounds__(256, 1) void gemm_bf16(
    const bf16* __restrict__ Ah, const bf16* __restrict__ Al,
    const bf16* __restrict__ Bh, const bf16* __restrict__ Bl,
    float* __restrict__ C, int M, int N, int K) {
  extern __shared__ char smraw[];
  uint32_t sb = (smem_u32(smraw) + 127) & ~127u;

  int t = threadIdx.x;
  int wid = t >> 5, l = t & 31;
  int wm = wid >> 2, wn = wid & 3;           // warp grid 2x4
  int bm = blockIdx.y * 128, bn = blockIdx.x * 128;
  int NC = K >> 5;

  // loader role
  int tile = t >> 6;            // 0 Ah, 1 Al, 2 Bh, 3 Bl
  int u = t & 63;
  const bf16* src = (tile == 0) ? Ah : (tile == 1) ? Al : (tile == 2) ? Bh : Bl;
  int row0 = (tile < 2) ? bm : bn;
  bool isB = tile >= 2;

  auto issue = [&](int c) {
    uint32_t dbase = sb + (c & 1) * BUF_B + tile * TILE_B;
    int k0 = c << 5;
#pragma unroll
    for (int i = 0; i < 8; i++) {
      int idx = u * 8 + i;            // 0..511
      int r = idx >> 2, ch = idx & 3;
      int grow = row0 + r;
      bool valid = !isB || (grow < N);
      const bf16* sp = valid ? (src + (size_t)grow * K + k0 + ch * 8)
                             : (src);
      cp16(dbase + r * 80 + ch * 16, sp, valid);
    }
    asm volatile("cp.async.commit_group;" ::: "memory");
  };

  float acc[4][4][4];
#pragma unroll
  for (int a = 0; a < 4; a++)
#pragma unroll
    for (int b = 0; b < 4; b++)
#pragma unroll
      for (int d = 0; d < 4; d++) acc[a][b][d] = 0.f;

  int grp = l >> 3, r8 = l & 7;
  // A frag address component (within a tile base)
  int aRow = wm * 64 + (grp & 1) * 8 + r8;     // + mt*16
  int aCol = (grp >> 1) * 16;                  // + ks*32
  // B frag address component
  int bRow = wn * 32 + (grp >> 1) * 8 + r8;    // + np*16
  int bCol = (grp & 1) * 16;                   // + ks*32

  issue(0);
  for (int c = 0; c < NC; c++) {
    if (c + 1 < NC) {
      issue(c + 1);
      asm volatile("cp.async.wait_group 1;" ::: "memory");
    } else {
      asm volatile("cp.async.wait_group 0;" ::: "memory");
    }
    __syncthreads();

    uint32_t base = sb + (c & 1) * BUF_B;
#pragma unroll
    for (int ks = 0; ks < 2; ks++) {
      uint32_t ah[4][4], al[4][4], bh[4][2], bl[4][2];
#pragma unroll
      for (int mt = 0; mt < 4; mt++) {
        uint32_t ad = base + (aRow + mt * 16) * 80 + aCol + ks * 32;
        ldsm4(ah[mt], ad);
        ldsm4(al[mt], ad + TILE_B);
      }
#pragma unroll
      for (int np = 0; np < 2; np++) {
        uint32_t bd = base + 2 * TILE_B + (bRow + np * 16) * 80 + bCol + ks * 32;
        uint32_t rh[4], rl[4];
        ldsm4(rh, bd);
        ldsm4(rl, bd + TILE_B);
        bh[np * 2][0] = rh[0]; bh[np * 2][1] = rh[1];
        bh[np * 2 + 1][0] = rh[2]; bh[np * 2 + 1][1] = rh[3];
        bl[np * 2][0] = rl[0]; bl[np * 2][1] = rl[1];
        bl[np * 2 + 1][0] = rl[2]; bl[np * 2 + 1][1] = rl[3];
      }
#pragma unroll
      for (int mi = 0; mi < 4; mi++)
#pragma unroll
        for (int ni = 0; ni < 4; ni++) {
          mma16816(acc[mi][ni], ah[mi], bh[ni]);
          mma16816(acc[mi][ni], ah[mi], bl[ni]);
          mma16816(acc[mi][ni], al[mi], bh[ni]);
        }
    }
    __syncthreads();
  }

  // epilogue
  int rb = bm + wm * 64 + (l >> 2);
  int cb = bn + wn * 32 + 2 * (l & 3);
#pragma unroll
  for (int mi = 0; mi < 4; mi++) {
#pragma unroll
    for (int ni = 0; ni < 4; ni++) {
      int cc = cb + ni * 8;
      if (cc < N) {
        int r0 = rb + mi * 16;
        *(float2*)&C[(size_t)r0 * N + cc] =
            make_float2(acc[mi][ni][0], acc[mi][ni][1]);
        *(float2*)&C[(size_t)(r0 + 8) * N + cc] =
            make_float2(acc[mi][ni][2], acc[mi][ni][3]);
      }
    }
  }
}

// ====================== depthwise causal conv (K=4) + SiLU ==================
__global__ void conv_silu_kernel(const float* __restrict__ x,
                                 const float* __restrict__ w,
                                 float* __restrict__ y) {
  int i = blockIdx.x * blockDim.x + threadIdx.x;
  if (i >= MTOT * CDIM) return;
  int c = i & (CDIM - 1);
  int bt = i >> 11;
  int t = bt & (T_LEN - 1);
  float acc = 0.f;
#pragma unroll
  for (int j = 0; j < 4; j++) {
    int ts = t + j - 3;
    float xv = (ts >= 0) ? x[i + (j - 3) * CDIM] : 0.f;
    acc = fmaf(xv, w[c * 4 + j], acc);
  }
  y[i] = acc / (1.f + __expf(-acc));  // silu
}

// ====================== prep: l2norm q/k, gate, beta ========================
__global__ void prep_kernel(float* __restrict__ q, float* __restrict__ k,
                            float* __restrict__ g, float* __restrict__ beta,
                            const float* __restrict__ A_log,
                            const float* __restrict__ dt_bias) {
  int blk = blockIdx.x;  // bt*16 + h
  int h = blk & 15;
  int bt = blk >> 4;
  int d = threadIdx.x;   // 0..127
  int idx = bt * CDIM + h * D_N + d;

  float qv = q[idx], kv = k[idx];
  float sq = qv * qv, sk = kv * kv;
#pragma unroll
  for (int o = 16; o > 0; o >>= 1) {
    sq += __shfl_xor_sync(0xffffffffu, sq, o);
    sk += __shfl_xor_sync(0xffffffffu, sk, o);
  }
  __shared__ float rq_[4], rk_[4];
  int wid = d >> 5, lane = d & 31;
  if (lane == 0) { rq_[wid] = sq; rk_[wid] = sk; }
  __syncthreads();
  float tq = rq_[0] + rq_[1] + rq_[2] + rq_[3];
  float tk = rk_[0] + rk_[1] + rk_[2] + rk_[3];

  q[idx] = qv * rsqrtf(tq + 1e-6f) * 0.08838834764831845f;  // D^-0.5
  k[idx] = kv * rsqrtf(tk + 1e-6f);

  float gp = g[idx] + dt_bias[h * D_N + d];
  float sp = (gp > 0.f) ? gp + log1pf(__expf(-gp)) : log1pf(__expf(gp));
  g[idx] = -__expf(A_log[h]) * sp;

  if (d == 0) {
    float bp = beta[bt * H_N + h];
    beta[bt * H_N + h] = 1.f / (1.f + __expf(-bp));
  }
}

// ====================== sequential gated delta-rule scan ====================
__global__ __launch_bounds__(128) void kda_scan_kernel(
    const float* __restrict__ q, const float* __restrict__ k,
    const float* __restrict__ v, const float* __restrict__ g,
    const float* __restrict__ beta, float* __restrict__ o) {
  int bh = blockIdx.x >> 2;
  int cg = blockIdx.x & 3;
  int b = bh >> 4, h = bh & 15;
  int tid = threadIdx.x;
  int cl = tid & 31;
  int rq = tid >> 5;
  int j = cg * 32 + cl;
  int rbase = rq * 32;

  __shared__ float ks[128], qs[128], es[128];
  __shared__ float vs[32], us[32];
  __shared__ float kp[4][32], op[4][32];
  __shared__ float beta_sh;

  float S[32];
#pragma unroll
  for (int i = 0; i < 32; i++) S[i] = 0.f;

  const size_t base = ((size_t)b * T_LEN) * CDIM + h * D_N;
  const size_t baseB = (size_t)b * T_LEN * H_N + h;

  float kr = k[base + tid];
  float qr = q[base + tid];
  float gr = g[base + tid];
  float vr = (tid < 32) ? v[base + j] : 0.f;
  float br = (tid == 0) ? beta[baseB] : 0.f;

  for (int t = 0; t < T_LEN; t++) {
    ks[tid] = kr;
    qs[tid] = qr;
    es[tid] = __expf(gr);
    if (tid < 32) vs[cl] = vr;
    if (tid == 0) beta_sh = br;
    __syncthreads();

    if (t + 1 < T_LEN) {
      size_t off2 = base + (size_t)(t + 1) * CDIM;
      kr = k[off2 + tid];
      qr = q[off2 + tid];
      gr = g[off2 + tid];
      if (tid < 32) vr = v[off2 + j];
      if (tid == 0) br = beta[baseB + (size_t)(t + 1) * H_N];
    }

    float kd = 0.f;
#pragma unroll
    for (int i = 0; i < 32; i += 4) {
      float4 e4 = *(const float4*)&es[rbase + i];
      float4 k4 = *(const float4*)&ks[rbase + i];
      S[i + 0] *= e4.x; kd = fmaf(k4.x, S[i + 0], kd);
      S[i + 1] *= e4.y; kd = fmaf(k4.y, S[i + 1], kd);
      S[i + 2] *= e4.z; kd = fmaf(k4.z, S[i + 2], kd);
      S[i + 3] *= e4.w; kd = fmaf(k4.w, S[i + 3], kd);
    }
    kp[rq][cl] = kd;
    __syncthreads();

    if (tid < 32) {
      float u = (vs[tid] - (kp[0][tid] + kp[1][tid] + kp[2][tid] + kp[3][tid])) * beta_sh;
      us[tid] = u;
    }
    __syncthreads();

    float u = us[cl];
    float od = 0.f;
#pragma unroll
    for (int i = 0; i < 32; i += 4) {
      float4 k4 = *(const float4*)&ks[rbase + i];
      float4 q4 = *(const float4*)&qs[rbase + i];
      S[i + 0] = fmaf(k4.x, u, S[i + 0]); od = fmaf(q4.x, S[i + 0], od);
      S[i + 1] = fmaf(k4.y, u, S[i + 1]); od = fmaf(q4.y, S[i + 1], od);
      S[i + 2] = fmaf(k4.z, u, S[i + 2]); od = fmaf(q4.z, S[i + 2], od);
      S[i + 3] = fmaf(k4.w, u, S[i + 3]); od = fmaf(q4.w, S[i + 3], od);
    }
    op[rq][cl] = od;
    __syncthreads();

    if (tid < 32)
      o[base + (size_t)t * CDIM + j] =
          op[0][tid] + op[1][tid] + op[2][tid] + op[3][tid];
  }
}

// ====================== gated RMSNorm ======================================
__global__ void gatenorm_kernel(const float* __restrict__ o,
                                const float* __restrict__ go,
                                const float* __restrict__ w,
                                float* __restrict__ out) {
  int blk = blockIdx.x;   // bt*16 + h
  int d = threadIdx.x;
  int idx = blk * D_N + d;
  float ov = o[idx];
  float s = ov * ov;
#pragma unroll
  for (int off = 16; off > 0; off >>= 1) s += __shfl_xor_sync(0xffffffffu, s, off);
  __shared__ float r_[4];
  int wid = d >> 5, lane = d & 31;
  if (lane == 0) r_[wid] = s;
  __syncthreads();
  float tot = r_[0] + r_[1] + r_[2] + r_[3];
  float rms = rsqrtf(tot * (1.f / 128.f) + 1e-6f);
  float gov = go[idx];
  out[idx] = ov * rms * w[d] * (1.f / (1.f + __expf(-gov)));
}

// ====================== launch =============================================
extern "C" void kernel_launch(void* const* d_in, const int* in_sizes, int n_in,
                              void* d_out, int out_size) {
  const float* x        = (const float*)d_in[0];
  const float* Wq       = (const float*)d_in[1];
  const float* Wk       = (const float*)d_in[2];
  const float* Wv       = (const float*)d_in[3];
  const float* conv_q_w = (const float*)d_in[4];
  const float* conv_k_w = (const float*)d_in[5];
  const float* conv_v_w = (const float*)d_in[6];
  const float* A_log    = (const float*)d_in[7];
  const float* Wfa      = (const float*)d_in[8];
  const float* Wfb      = (const float*)d_in[9];
  const float* dt_bias  = (const float*)d_in[10];
  const float* Wb       = (const float*)d_in[11];
  const float* Wga      = (const float*)d_in[12];
  const float* Wgb      = (const float*)d_in[13];
  const float* o_norm_w = (const float*)d_in[14];
  const float* Wo       = (const float*)d_in[15];
  float* out = (float*)d_out;

  float *bq, *bk, *bv, *cq, *ck, *cv, *gate, *gog, *fa, *ga, *beta, *oscan, *ogated;
  cudaGetSymbolAddress((void**)&bq, g_bufq);
  cudaGetSymbolAddress((void**)&bk, g_bufk);
  cudaGetSymbolAddress((void**)&bv, g_bufv);
  cudaGetSymbolAddress((void**)&cq, g_cq);
  cudaGetSymbolAddress((void**)&ck, g_ck);
  cudaGetSymbolAddress((void**)&cv, g_cv);
  cudaGetSymbolAddress((void**)&gate, g_gate);
  cudaGetSymbolAddress((void**)&gog, g_gog);
  cudaGetSymbolAddress((void**)&fa, g_fa);
  cudaGetSymbolAddress((void**)&ga, g_ga);
  cudaGetSymbolAddress((void**)&beta, g_beta);
  cudaGetSymbolAddress((void**)&oscan, g_oscan);
  cudaGetSymbolAddress((void**)&ogated, g_ogated);

  bf16 *xh, *xl, *oh, *ol, *fah, *fal, *gah, *gal;
  bf16 *WqTh, *WqTl, *WkTh, *WkTl, *WvTh, *WvTl, *WoTh, *WoTl;
  bf16 *WfaTh, *WfaTl, *WgaTh, *WgaTl, *WfbTh, *WfbTl, *WgbTh, *WgbTl;
  bf16 *WbTh, *WbTl;
  cudaGetSymbolAddress((void**)&xh, g_xh);
  cudaGetSymbolAddress((void**)&xl, g_xl);
  cudaGetSymbolAddress((void**)&oh, g_oh);
  cudaGetSymbolAddress((void**)&ol, g_ol);
  cudaGetSymbolAddress((void**)&fah, g_fah);
  cudaGetSymbolAddress((void**)&fal, g_fal);
  cudaGetSymbolAddress((void**)&gah, g_gah);
  cudaGetSymbolAddress((void**)&gal, g_gal);
  cudaGetSymbolAddress((void**)&WqTh, g_WqTh);
  cudaGetSymbolAddress((void**)&WqTl, g_WqTl);
  cudaGetSymbolAddress((void**)&WkTh, g_WkTh);
  cudaGetSymbolAddress((void**)&WkTl, g_WkTl);
  cudaGetSymbolAddress((void**)&WvTh, g_WvTh);
  cudaGetSymbolAddress((void**)&WvTl, g_WvTl);
  cudaGetSymbolAddress((void**)&WoTh, g_WoTh);
  cudaGetSymbolAddress((void**)&WoTl, g_WoTl);
  cudaGetSymbolAddress((void**)&WfaTh, g_WfaTh);
  cudaGetSymbolAddress((void**)&WfaTl, g_WfaTl);
  cudaGetSymbolAddress((void**)&WgaTh, g_WgaTh);
  cudaGetSymbolAddress((void**)&WgaTl, g_WgaTl);
  cudaGetSymbolAddress((void**)&WfbTh, g_WfbTh);
  cudaGetSymbolAddress((void**)&WfbTl, g_WfbTl);
  cudaGetSymbolAddress((void**)&WgbTh, g_WgbTh);
  cudaGetSymbolAddress((void**)&WgbTl, g_WgbTl);
  cudaGetSymbolAddress((void**)&WbTh, g_WbTh);
  cudaGetSymbolAddress((void**)&WbTl, g_WbTl);

  constexpr int GSMEM = 2 * BUF_B + 256;   // 82176
  cudaFuncSetAttribute(gemm_bf16, cudaFuncAttributeMaxDynamicSharedMemorySize, GSMEM);

  dim3 tb(32, 8);
  // weight transposes + bf16 split
  transpose_split<<<dim3(64, 64), tb>>>(Wq, WqTh, WqTl, CDIM, CDIM);
  transpose_split<<<dim3(64, 64), tb>>>(Wk, WkTh, WkTl, CDIM, CDIM);
  transpose_split<<<dim3(64, 64), tb>>>(Wv, WvTh, WvTl, CDIM, CDIM);
  transpose_split<<<dim3(64, 64), tb>>>(Wo, WoTh, WoTl, CDIM, CDIM);
  transpose_split<<<dim3(4, 64), tb>>>(Wfa, WfaTh, WfaTl, CDIM, D_N);
  transpose_split<<<dim3(4, 64), tb>>>(Wga, WgaTh, WgaTl, CDIM, D_N);
  transpose_split<<<dim3(64, 4), tb>>>(Wfb, WfbTh, WfbTl, D_N, CDIM);
  transpose_split<<<dim3(64, 4), tb>>>(Wgb, WgbTh, WgbTl, D_N, CDIM);
  transpose_split<<<dim3(1, 64), tb>>>(Wb, WbTh, WbTl, CDIM, H_N);

  // split x
  int nx = MTOT * CDIM;
  split_kernel<<<nx / 1024, 256>>>(x, xh, xl, nx);

  dim3 gBig(CDIM / 128, MTOT / 128);   // (16, 64)
  dim3 gN1(1, MTOT / 128);             // (1, 64)

  // projections (tensor cores via mma.sync)
  gemm_bf16<<<gBig, 256, GSMEM>>>(xh, xl, WqTh, WqTl, bq, MTOT, CDIM, CDIM);
  gemm_bf16<<<gBig, 256, GSMEM>>>(xh, xl, WkTh, WkTl, bk, MTOT, CDIM, CDIM);
  gemm_bf16<<<gBig, 256, GSMEM>>>(xh, xl, WvTh, WvTl, bv, MTOT, CDIM, CDIM);
  // low-rank gate paths
  gemm_bf16<<<gN1, 256, GSMEM>>>(xh, xl, WfaTh, WfaTl, fa, MTOT, D_N, CDIM);
  split_kernel<<<MTOT * D_N / 1024, 256>>>(fa, fah, fal, MTOT * D_N);
  gemm_bf16<<<gBig, 256, GSMEM>>>(fah, fal, WfbTh, WfbTl, gate, MTOT, CDIM, D_N);
  gemm_bf16<<<gN1, 256, GSMEM>>>(xh, xl, WgaTh, WgaTl, ga, MTOT, D_N, CDIM);
  split_kernel<<<MTOT * D_N / 1024, 256>>>(ga, gah, gal, MTOT * D_N);
  gemm_bf16<<<gBig, 256, GSMEM>>>(gah, gal, WgbTh, WgbTl, gog, MTOT, CDIM, D_N);
  // beta pre-activation (N=16, zfill + store guards)
  gemm_bf16<<<gN1, 256, GSMEM>>>(xh, xl, WbTh, WbTl, beta, MTOT, H_N, CDIM);

  // conv + silu
  conv_silu_kernel<<<(nx + 255) / 256, 256>>>(bq, conv_q_w, cq);
  conv_silu_kernel<<<(nx + 255) / 256, 256>>>(bk, conv_k_w, ck);
  conv_silu_kernel<<<(nx + 255) / 256, 256>>>(bv, conv_v_w, cv);

  // normalize q/k, finalize gate + beta
  prep_kernel<<<MTOT * H_N, 128>>>(cq, ck, gate, beta, A_log, dt_bias);

  // sequential scan
  kda_scan_kernel<<<128, 128>>>(cq, ck, cv, gate, beta, oscan);

  // gated rmsnorm
  gatenorm_kernel<<<MTOT * H_N, 128>>>(oscan, gog, o_norm_w, ogated);

  // output projection
  split_kernel<<<nx / 1024, 256>>>(ogated, oh, ol, nx);
  gemm_bf16<<<gBig, 256, GSMEM>>>(oh, ol, WoTh, WoTl, out, MTOT, CDIM, CDIM);
}